// round 15
// baseline (speedup 1.0000x reference)
#include <cuda_runtime.h>
#include <cuda_fp16.h>
#include <cstdint>

#define NI 9
#define NM3 165
#define NM2 45
#define ST3 32
#define CDIM 256
#define EDIM 10
#define NROWB 80              // B rows: hi 0..39 (ch*10+e), lo 40..79
#define NWORDS 112            // 224 fp16 = 112 u32 words per row
#define RSTRIDE 116           // row stride in u32 words — ldmatrix conflict-free
#define NT 4                  // b-tiles per CTA (B reused; A/y double-buffered)
#define ABUF 59392            // one A buffer: 128*116*4
#define SMB_OFF 118784        // B after 2 A buffers
#define SMY_OFF 155904        // y[2][1280] after B
#define SMTOT 166144

__device__ __align__(16) float g_T3[4][NM3 * ST3];
__device__ __align__(16) float g_T2[4][NM2 * 4];
__device__ __align__(16) uint32_t g_H[CDIM * NROWB * NWORDS];   // 9.2 MB

// ---------------- proven symmetrization precompute ----------------
__device__ __forceinline__ void decode3(int m, int& i, int& j, int& l) {
    int cnt = 0;
    for (int a = 0; a < NI; a++) for (int b = a; b < NI; b++) for (int c = b; c < NI; c++) {
        if (cnt == m) { i = a; j = b; l = c; return; } cnt++;
    }
    i = j = l = 0;
}
__device__ __forceinline__ void decode2(int m, int& i, int& j) {
    int cnt = 0;
    for (int a = 0; a < NI; a++) for (int b = a; b < NI; b++) {
        if (cnt == m) { i = a; j = b; return; } cnt++;
    }
    i = j = 0;
}
__global__ void precompute_kernel(const float* __restrict__ U2s, const float* __restrict__ U3s,
                                  const float* __restrict__ U2v, const float* __restrict__ U3v) {
    int t = blockIdx.x * blockDim.x + threadIdx.x;
    const int N3 = 4 * NM3 * ST3, N2 = 4 * NM2 * 4;
    if (t < N3) {
        int pass = t / (NM3 * ST3), r = t % (NM3 * ST3), m = r / ST3, k = r % ST3;
        int K = (pass == 0) ? 23 : 30;
        float val = 0.f;
        if (k < K) {
            int i, j, l; decode3(m, i, j, l);
            int pi[6] = { i, i, j, j, l, l }, pj[6] = { j, l, i, l, i, j }, pl[6] = { l, j, l, i, j, i };
            const float* base = (pass == 0) ? U3s : (U3v + (pass - 1) * (NI * NI * NI * 30));
            int codes[6];
            for (int q = 0; q < 6; q++) {
                int code = (pi[q] * NI + pj[q]) * NI + pl[q];
                bool dup = false;
                for (int u = 0; u < q; u++) if (codes[u] == code) dup = true;
                codes[q] = code;
                if (!dup) val += base[code * K + k];
            }
        }
        g_T3[pass][m * ST3 + k] = val;
    } else if (t < N3 + N2) {
        int u = t - N3, pass = u / (NM2 * 4), r = u % (NM2 * 4), m = r / 4, k = r % 4;
        int K = (pass == 0) ? 3 : 4;
        float val = 0.f;
        if (k < K) {
            int i, j; decode2(m, i, j);
            const float* base = (pass == 0) ? U2s : (U2v + (pass - 1) * (NI * NI * 4));
            val = base[(i * NI + j) * K + k];
            if (i != j) val += base[(j * NI + i) * K + k];
        }
        g_T2[pass][m * 4 + k] = val;
    }
}

// ---------------- H build: fp16 hi rows 0..39, fp16 residual lo rows 40..79 ----------------
__global__ void __launch_bounds__(192)
hbuild_kernel(const float* __restrict__ U1s, const float* __restrict__ U1v,
              const float* __restrict__ W1s, const float* __restrict__ W2s,
              const float* __restrict__ W3s, const float* __restrict__ W1v,
              const float* __restrict__ W2v, const float* __restrict__ W3v) {
    const int c = blockIdx.x >> 2, ch = blockIdx.x & 3;
    const int tid = threadIdx.x;
    __shared__ float sT3[NM3 * 33];
    __shared__ float sT2[NM2 * 4];
    __shared__ float sW3[12 * 30], sW2[12 * 4], sW1[12], sU1[9];

    const int K3 = ch ? 30 : 23, K2 = ch ? 4 : 3;
    const float* W3 = ch ? W3v : W3s;
    const float* W2 = ch ? W2v : W2s;
    const float* W1 = ch ? W1v : W1s;
    const float* U1 = ch ? (U1v + (ch - 1) * NI) : U1s;

    for (int idx = tid; idx < NM3 * 32; idx += 192)
        sT3[(idx >> 5) * 33 + (idx & 31)] = g_T3[ch][idx];
    for (int idx = tid; idx < NM2 * 4; idx += 192) sT2[idx] = g_T2[ch][idx];
    for (int idx = tid; idx < 12 * 30; idx += 192) {
        int e = idx / 30, kk = idx % 30;
        sW3[idx] = (e < EDIM && kk < K3) ? W3[(e * K3 + kk) * CDIM + c] : 0.f;
    }
    if (tid < 48) {
        int e = tid >> 2, kk = tid & 3;
        sW2[tid] = (e < EDIM && kk < K2) ? W2[(e * K2 + kk) * CDIM + c] : 0.f;
    }
    if (tid < 12) sW1[tid] = (tid < EDIM) ? W1[tid * CDIM + c] : 0.f;
    if (tid < 9) sU1[tid] = U1[tid];
    __syncthreads();

    const int e = tid / 16, t16 = tid % 16;
    if (e >= EDIM) return;
    const int n = ch * EDIM + e;
    uint32_t* dstH = g_H + ((size_t)c * NROWB + n) * NWORDS;
    uint32_t* dstL = g_H + ((size_t)c * NROWB + 40 + n) * NWORDS;
    for (int it = 0; it < 7; it++) {
        int t = t16 + it * 16;
        float v[2];
#pragma unroll
        for (int h = 0; h < 2; h++) {
            int m = 2 * t + h;
            float s = 0.f;
            if (m < 219) {
                if (m < 165) {
                    for (int kk = 0; kk < 30; kk++) s += sT3[m * 33 + kk] * sW3[e * 30 + kk];
                } else if (m < 210) {
                    int q = m - 165;
                    for (int kk = 0; kk < 4; kk++) s += sT2[q * 4 + kk] * sW2[e * 4 + kk];
                } else {
                    s = sU1[m - 210] * sW1[e];
                }
            }
            v[h] = s;
        }
        __half h0 = __float2half_rn(v[0]), h1 = __float2half_rn(v[1]);
        __half l0 = __float2half_rn(v[0] - __half2float(h0));
        __half l1 = __float2half_rn(v[1] - __half2float(h1));
        __half2 hh, ll; hh.x = h0; hh.y = h1; ll.x = l0; ll.y = l1;
        dstH[t] = *reinterpret_cast<uint32_t*>(&hh);
        dstL[t] = *reinterpret_cast<uint32_t*>(&ll);
    }
}

// ---------------- compile-time monomial maps for the A operand ----------------
__host__ __device__ constexpr int tri_p(int m) {
    int c = 0;
    for (int i = 0; i < 9; i++) for (int j = i; j < 9; j++) for (int l = j; l < 9; l++) {
        if (c == m) return i * 9 - i * (i - 1) / 2 + (j - i);
        c++;
    }
    return 0;
}
__host__ __device__ constexpr int tri_l(int m) {
    int c = 0;
    for (int i = 0; i < 9; i++) for (int j = i; j < 9; j++) for (int l = j; l < 9; l++) {
        if (c == m) return l;
        c++;
    }
    return 0;
}
template <int M>
__device__ __forceinline__ float elemv(const float* p, const float* xr) {
    if constexpr (M < 165) { constexpr int pi = tri_p(M), li = tri_l(M); return p[pi] * xr[li]; }
    else if constexpr (M < 210) return p[M - 165];
    else if constexpr (M < 219) return xr[M - 210];
    else return 0.f;
}
__device__ __forceinline__ uint32_t pack_f16(float v0, float v1) {
    uint32_t w;
    asm("cvt.rn.f16x2.f32 %0, %1, %2;" : "=r"(w) : "f"(v1), "f"(v0));
    return w;
}
template <int G, int G1>
__device__ __forceinline__ void build_range(uint4* dst, const float* p, const float* xr) {
    if constexpr (G < G1) {
        uint4 w;
        w.x = pack_f16(elemv<8 * G + 0>(p, xr), elemv<8 * G + 1>(p, xr));
        w.y = pack_f16(elemv<8 * G + 2>(p, xr), elemv<8 * G + 3>(p, xr));
        w.z = pack_f16(elemv<8 * G + 4>(p, xr), elemv<8 * G + 5>(p, xr));
        w.w = pack_f16(elemv<8 * G + 6>(p, xr), elemv<8 * G + 7>(p, xr));
        dst[G] = w;
        build_range<G + 1, G1>(dst, p, xr);
    }
}

// ---------------- mma helpers ----------------
__device__ __forceinline__ uint32_t s2u(const void* p) {
    uint32_t a;
    asm("{ .reg .u64 t; cvta.to.shared.u64 t, %1; cvt.u32.u64 %0, t; }" : "=r"(a) : "l"(p));
    return a;
}
#define LDSM4(r, addr) asm volatile( \
    "ldmatrix.sync.aligned.m8n8.x4.shared.b16 {%0,%1,%2,%3}, [%4];" \
    : "=r"((r)[0]), "=r"((r)[1]), "=r"((r)[2]), "=r"((r)[3]) : "r"(addr))
#define MMA16816(d, a, b0, b1) asm volatile( \
    "mma.sync.aligned.m16n8k16.row.col.f32.f16.f16.f32 " \
    "{%0,%1,%2,%3},{%4,%5,%6,%7},{%8,%9},{%0,%1,%2,%3};" \
    : "+f"((d)[0]), "+f"((d)[1]), "+f"((d)[2]), "+f"((d)[3]) \
    : "r"((a)[0]), "r"((a)[1]), "r"((a)[2]), "r"((a)[3]), "r"(b0), "r"(b1))

// ---------------- main kernel: 256 thr, 1 CTA/SM, double-buffered A/y ----------------
__global__ void __launch_bounds__(256)
sc_mma_kernel(const float* __restrict__ x, const float* __restrict__ y,
              float* __restrict__ out) {
    extern __shared__ __align__(16) char smem[];
    uint32_t* B32 = (uint32_t*)(smem + SMB_OFF);
    float* syb = (float*)(smem + SMY_OFF);   // [2][1280]

    const int tid = threadIdx.x;
    const int lane = tid & 31, warp = tid >> 5;   // 8 warps, 16 rows each
    const int c = blockIdx.y;
    const uint32_t sbA = s2u(smem), sbB = s2u(B32);
    const int row = tid >> 1, half = tid & 1;

    // stage B once (80 rows x 28 uint4) — reused across NT b-tiles
    {
        const uint4* src = (const uint4*)(g_H + (size_t)c * NROWB * NWORDS);
        for (int t = tid; t < NROWB * (NWORDS / 4); t += 256) {
            int r = t / (NWORDS / 4), q = t % (NWORDS / 4);
            *(uint4*)((uint32_t*)smem + SMB_OFF / 4 + r * RSTRIDE + q * 4) = src[t];
        }
    }

    // prologue: tile 0 — x regs, build A into buf0, stage y(0)
    float xr[NI];
    {
        const int b0 = (blockIdx.x * NT) << 7;
        const float* xp = x + ((size_t)(b0 + row) * CDIM + c) * NI;
#pragma unroll
        for (int i = 0; i < NI; i++) xr[i] = xp[i];
        float p[45];
        int pc = 0;
#pragma unroll
        for (int i = 0; i < NI; i++)
#pragma unroll
            for (int j = i; j < NI; j++) p[pc++] = xr[i] * xr[j];
        uint4* dst = (uint4*)((uint32_t*)smem + row * RSTRIDE);
        if (half == 0) build_range<0, 14>(dst, p, xr);
        else           build_range<14, 28>(dst, p, xr);
        for (int u = tid; u < 128 * EDIM; u += 256)
            syb[u] = y[(size_t)b0 * EDIM + u];
    }
    __syncthreads();

    const uint32_t aoff = ((uint32_t)(lane & 15)) * RSTRIDE * 4 + ((lane >> 4) << 4);
    const uint32_t boff = ((uint32_t)((lane & 7) + ((lane >> 4) << 3))) * RSTRIDE * 4 +
                          (((lane >> 3) & 1) << 4);
    const int g = lane >> 2, tig = lane & 3;
    const int r0 = warp * 16 + g;

    for (int t = 0; t < NT; t++) {
        const int cur = t & 1, nxt = cur ^ 1;
        const int b0 = (blockIdx.x * NT + t) << 7;
        const bool more = (t + 1 < NT);

        // prefetch next tile's x into registers (hidden under MMA loop)
        float xn[NI];
        if (more) {
            const float* xp = x + ((size_t)(b0 + 128 + row) * CDIM + c) * NI;
#pragma unroll
            for (int i = 0; i < NI; i++) xn[i] = xp[i];
        }

        float acc[10][4];
#pragma unroll
        for (int n = 0; n < 10; n++)
#pragma unroll
            for (int d = 0; d < 4; d++) acc[n][d] = 0.f;

        const uint32_t abase = sbA + (uint32_t)cur * ABUF +
                               (uint32_t)(warp * 16) * RSTRIDE * 4 + aoff;
        // single pass over K, N=80 (hi cols 0..39, lo cols 40..79)
#pragma unroll 2
        for (int k = 0; k < 14; k++) {
            uint32_t af[4], bf[5][4];
            LDSM4(af, abase + k * 32);
#pragma unroll
            for (int gq = 0; gq < 5; gq++)
                LDSM4(bf[gq], sbB + (uint32_t)(gq * 16) * RSTRIDE * 4 + k * 32 + boff);
#pragma unroll
            for (int np = 0; np < 10; np++)
                MMA16816(acc[np], af, bf[np >> 1][(np & 1) * 2], bf[np >> 1][(np & 1) * 2 + 1]);
        }

        // build next A into the other buffer + stage next y (overlaps MMA drain)
        if (more) {
            float p[45];
            int pc = 0;
#pragma unroll
            for (int i = 0; i < NI; i++)
#pragma unroll
                for (int j = i; j < NI; j++) p[pc++] = xn[i] * xn[j];
            uint4* dst = (uint4*)((uint32_t*)smem + nxt * (ABUF / 4) + row * RSTRIDE);
            if (half == 0) build_range<0, 14>(dst, p, xn);
            else           build_range<14, 28>(dst, p, xn);
            for (int u = tid; u < 128 * EDIM; u += 256)
                syb[nxt * 1280 + u] = y[(size_t)(b0 + 128) * EDIM + u];
        }

        // epilogue: scale by y(cur), fold lo onto hi, reduce across tig lanes
        const float* sy = syb + cur * 1280;
        float res[2][4] = { {0.f, 0.f, 0.f, 0.f}, {0.f, 0.f, 0.f, 0.f} };
#pragma unroll
        for (int np = 0; np < 10; np++) {
            const int base = (np < 5) ? np * 8 : np * 8 - 40;
            int m0 = base + tig * 2, m1 = m0 + 1;
            int ch0 = m0 / EDIM, e0 = m0 % EDIM;
            int ch1 = m1 / EDIM, e1 = m1 % EDIM;
            res[0][ch0] += acc[np][0] * sy[r0 * EDIM + e0];
            res[0][ch1] += acc[np][1] * sy[r0 * EDIM + e1];
            res[1][ch0] += acc[np][2] * sy[(r0 + 8) * EDIM + e0];
            res[1][ch1] += acc[np][3] * sy[(r0 + 8) * EDIM + e1];
        }
#pragma unroll
        for (int d = 1; d <= 2; d <<= 1)
#pragma unroll
            for (int h = 0; h < 2; h++)
#pragma unroll
                for (int q = 0; q < 4; q++)
                    res[h][q] += __shfl_xor_sync(0xffffffffu, res[h][q], d);

        if (tig == 0) {
#pragma unroll
            for (int h = 0; h < 2; h++) {
                size_t b = (size_t)(b0 + r0 + h * 8);
                out[b * 1024 + c] = res[h][0];
                out[b * 1024 + 256 + c * 3 + 0] = res[h][1];
                out[b * 1024 + 256 + c * 3 + 1] = res[h][2];
                out[b * 1024 + 256 + c * 3 + 2] = res[h][3];
            }
        }

        __syncthreads();   // next-buffer writes visible before next tile's LDSM
    }
}

extern "C" void kernel_launch(void* const* d_in, const int* in_sizes, int n_in,
                              void* d_out, int out_size) {
    const float* x   = (const float*)d_in[0];
    const float* y   = (const float*)d_in[1];
    const float* U1s = (const float*)d_in[2];
    const float* U2s = (const float*)d_in[3];
    const float* U3s = (const float*)d_in[4];
    const float* U1v = (const float*)d_in[5];
    const float* U2v = (const float*)d_in[6];
    const float* U3v = (const float*)d_in[7];
    const float* W1s = (const float*)d_in[8];
    const float* W2s = (const float*)d_in[9];
    const float* W3s = (const float*)d_in[10];
    const float* W1v = (const float*)d_in[11];
    const float* W2v = (const float*)d_in[12];
    const float* W3v = (const float*)d_in[13];
    float* out = (float*)d_out;

    const int B = in_sizes[0] / (CDIM * NI);  // 2048
    const int ntile = B / 128;                 // 16

    cudaFuncSetAttribute(sc_mma_kernel, cudaFuncAttributeMaxDynamicSharedMemorySize, SMTOT);

    const int total = 4 * NM3 * ST3 + 4 * NM2 * 4;
    precompute_kernel<<<(total + 255) / 256, 256>>>(U2s, U3s, U2v, U3v);
    hbuild_kernel<<<CDIM * 4, 192>>>(U1s, U1v, W1s, W2s, W3s, W1v, W2v, W3v);
    sc_mma_kernel<<<dim3(ntile / NT, CDIM), 256, SMTOT>>>(x, y, out);
}

// round 16
// speedup vs baseline: 1.3556x; 1.3556x over previous
#include <cuda_runtime.h>
#include <cuda_fp16.h>
#include <cstdint>

#define NI 9
#define NM3 165
#define NM2 45
#define ST3 32
#define CDIM 256
#define EDIM 10
#define NROWB 48              // B rows: n = ch*12 + e (e>=10 zero pad), fp16 hi only
#define NWORDS 112            // 224 fp16 = 112 u32 words per row
#define RSTRIDE 116           // row stride in u32 words — ldmatrix conflict-free
#define NT 4                  // b-tiles per CTA (B reused across tiles)
#define SMB 59392             // A: 128*116*4
#define SMY 81664             // B: 48*116*4 = 22272
#define SMTOT 87808           // + y: 128*12*4 = 6144

__device__ __align__(16) float g_T3[4][NM3 * ST3];
__device__ __align__(16) float g_T2[4][NM2 * 4];
__device__ __align__(16) uint32_t g_H[CDIM * NROWB * NWORDS];   // 5.5 MB

// ---------------- proven symmetrization precompute ----------------
__device__ __forceinline__ void decode3(int m, int& i, int& j, int& l) {
    int cnt = 0;
    for (int a = 0; a < NI; a++) for (int b = a; b < NI; b++) for (int c = b; c < NI; c++) {
        if (cnt == m) { i = a; j = b; l = c; return; } cnt++;
    }
    i = j = l = 0;
}
__device__ __forceinline__ void decode2(int m, int& i, int& j) {
    int cnt = 0;
    for (int a = 0; a < NI; a++) for (int b = a; b < NI; b++) {
        if (cnt == m) { i = a; j = b; return; } cnt++;
    }
    i = j = 0;
}
__global__ void precompute_kernel(const float* __restrict__ U2s, const float* __restrict__ U3s,
                                  const float* __restrict__ U2v, const float* __restrict__ U3v) {
    int t = blockIdx.x * blockDim.x + threadIdx.x;
    const int N3 = 4 * NM3 * ST3, N2 = 4 * NM2 * 4;
    if (t < N3) {
        int pass = t / (NM3 * ST3), r = t % (NM3 * ST3), m = r / ST3, k = r % ST3;
        int K = (pass == 0) ? 23 : 30;
        float val = 0.f;
        if (k < K) {
            int i, j, l; decode3(m, i, j, l);
            int pi[6] = { i, i, j, j, l, l }, pj[6] = { j, l, i, l, i, j }, pl[6] = { l, j, l, i, j, i };
            const float* base = (pass == 0) ? U3s : (U3v + (pass - 1) * (NI * NI * NI * 30));
            int codes[6];
            for (int q = 0; q < 6; q++) {
                int code = (pi[q] * NI + pj[q]) * NI + pl[q];
                bool dup = false;
                for (int u = 0; u < q; u++) if (codes[u] == code) dup = true;
                codes[q] = code;
                if (!dup) val += base[code * K + k];
            }
        }
        g_T3[pass][m * ST3 + k] = val;
    } else if (t < N3 + N2) {
        int u = t - N3, pass = u / (NM2 * 4), r = u % (NM2 * 4), m = r / 4, k = r % 4;
        int K = (pass == 0) ? 3 : 4;
        float val = 0.f;
        if (k < K) {
            int i, j; decode2(m, i, j);
            const float* base = (pass == 0) ? U2s : (U2v + (pass - 1) * (NI * NI * 4));
            val = base[(i * NI + j) * K + k];
            if (i != j) val += base[(j * NI + i) * K + k];
        }
        g_T2[pass][m * 4 + k] = val;
    }
}

// ---------------- H build: fp16 hi only, rows n = ch*12 + e (e>=10 zeros) ----------------
__global__ void __launch_bounds__(192)
hbuild_kernel(const float* __restrict__ U1s, const float* __restrict__ U1v,
              const float* __restrict__ W1s, const float* __restrict__ W2s,
              const float* __restrict__ W3s, const float* __restrict__ W1v,
              const float* __restrict__ W2v, const float* __restrict__ W3v) {
    const int c = blockIdx.x >> 2, ch = blockIdx.x & 3;
    const int tid = threadIdx.x;
    __shared__ float sT3[NM3 * 33];
    __shared__ float sT2[NM2 * 4];
    __shared__ float sW3[12 * 30], sW2[12 * 4], sW1[12], sU1[9];

    const int K3 = ch ? 30 : 23, K2 = ch ? 4 : 3;
    const float* W3 = ch ? W3v : W3s;
    const float* W2 = ch ? W2v : W2s;
    const float* W1 = ch ? W1v : W1s;
    const float* U1 = ch ? (U1v + (ch - 1) * NI) : U1s;

    for (int idx = tid; idx < NM3 * 32; idx += 192)
        sT3[(idx >> 5) * 33 + (idx & 31)] = g_T3[ch][idx];
    for (int idx = tid; idx < NM2 * 4; idx += 192) sT2[idx] = g_T2[ch][idx];
    for (int idx = tid; idx < 12 * 30; idx += 192) {
        int e = idx / 30, kk = idx % 30;
        sW3[idx] = (e < EDIM && kk < K3) ? W3[(e * K3 + kk) * CDIM + c] : 0.f;
    }
    if (tid < 48) {
        int e = tid >> 2, kk = tid & 3;
        sW2[tid] = (e < EDIM && kk < K2) ? W2[(e * K2 + kk) * CDIM + c] : 0.f;
    }
    if (tid < 12) sW1[tid] = (tid < EDIM) ? W1[tid * CDIM + c] : 0.f;
    if (tid < 9) sU1[tid] = U1[tid];
    __syncthreads();

    const int e = tid / 16, t16 = tid % 16;   // e = 0..11 (rows e>=10 get zeros)
    const int n = ch * 12 + e;
    uint32_t* dstH = g_H + ((size_t)c * NROWB + n) * NWORDS;
    for (int it = 0; it < 7; it++) {
        int t = t16 + it * 16;
        float v[2];
#pragma unroll
        for (int h = 0; h < 2; h++) {
            int m = 2 * t + h;
            float s = 0.f;
            if (e < EDIM && m < 219) {
                if (m < 165) {
                    for (int kk = 0; kk < 30; kk++) s += sT3[m * 33 + kk] * sW3[e * 30 + kk];
                } else if (m < 210) {
                    int q = m - 165;
                    for (int kk = 0; kk < 4; kk++) s += sT2[q * 4 + kk] * sW2[e * 4 + kk];
                } else {
                    s = sU1[m - 210] * sW1[e];
                }
            }
            v[h] = s;
        }
        __half h0 = __float2half_rn(v[0]), h1 = __float2half_rn(v[1]);
        __half2 hh; hh.x = h0; hh.y = h1;
        dstH[t] = *reinterpret_cast<uint32_t*>(&hh);
    }
}

// ---------------- compile-time monomial maps for the A operand ----------------
__host__ __device__ constexpr int tri_p(int m) {
    int c = 0;
    for (int i = 0; i < 9; i++) for (int j = i; j < 9; j++) for (int l = j; l < 9; l++) {
        if (c == m) return i * 9 - i * (i - 1) / 2 + (j - i);
        c++;
    }
    return 0;
}
__host__ __device__ constexpr int tri_l(int m) {
    int c = 0;
    for (int i = 0; i < 9; i++) for (int j = i; j < 9; j++) for (int l = j; l < 9; l++) {
        if (c == m) return l;
        c++;
    }
    return 0;
}
template <int M>
__device__ __forceinline__ float elemv(const float* p, const float* xr) {
    if constexpr (M < 165) { constexpr int pi = tri_p(M), li = tri_l(M); return p[pi] * xr[li]; }
    else if constexpr (M < 210) return p[M - 165];
    else if constexpr (M < 219) return xr[M - 210];
    else return 0.f;
}
__device__ __forceinline__ uint32_t pack_f16(float v0, float v1) {
    uint32_t w;
    asm("cvt.rn.f16x2.f32 %0, %1, %2;" : "=r"(w) : "f"(v1), "f"(v0));
    return w;
}
template <int G, int G1>
__device__ __forceinline__ void build_range(uint4* dst, const float* p, const float* xr) {
    if constexpr (G < G1) {
        uint4 w;
        w.x = pack_f16(elemv<8 * G + 0>(p, xr), elemv<8 * G + 1>(p, xr));
        w.y = pack_f16(elemv<8 * G + 2>(p, xr), elemv<8 * G + 3>(p, xr));
        w.z = pack_f16(elemv<8 * G + 4>(p, xr), elemv<8 * G + 5>(p, xr));
        w.w = pack_f16(elemv<8 * G + 6>(p, xr), elemv<8 * G + 7>(p, xr));
        dst[G] = w;
        build_range<G + 1, G1>(dst, p, xr);
    }
}

// ---------------- mma helpers ----------------
__device__ __forceinline__ uint32_t s2u(const void* p) {
    uint32_t a;
    asm("{ .reg .u64 t; cvta.to.shared.u64 t, %1; cvt.u32.u64 %0, t; }" : "=r"(a) : "l"(p));
    return a;
}
#define LDSM4(r, addr) asm volatile( \
    "ldmatrix.sync.aligned.m8n8.x4.shared.b16 {%0,%1,%2,%3}, [%4];" \
    : "=r"((r)[0]), "=r"((r)[1]), "=r"((r)[2]), "=r"((r)[3]) : "r"(addr))
#define MMA16816(d, a, b0, b1) asm volatile( \
    "mma.sync.aligned.m16n8k16.row.col.f32.f16.f16.f32 " \
    "{%0,%1,%2,%3},{%4,%5,%6,%7},{%8,%9},{%0,%1,%2,%3};" \
    : "+f"((d)[0]), "+f"((d)[1]), "+f"((d)[2]), "+f"((d)[3]) \
    : "r"((a)[0]), "r"((a)[1]), "r"((a)[2]), "r"((a)[3]), "r"(b0), "r"(b1))

// ---------------- main kernel: 256 threads, CTA = (4 b-tiles, c), B hi-only ----------------
__global__ void __launch_bounds__(256)
sc_mma_kernel(const float* __restrict__ x, const float* __restrict__ y,
              float* __restrict__ out) {
    extern __shared__ __align__(16) char smem[];
    uint32_t* A32 = (uint32_t*)smem;
    uint32_t* B32 = (uint32_t*)(smem + SMB);
    float* sy = (float*)(smem + SMY);   // [128][12], e>=10 zero

    const int tid = threadIdx.x;
    const int lane = tid & 31, warp = tid >> 5;   // 8 warps, 16 rows each
    const int c = blockIdx.y;
    const uint32_t sbA = s2u(A32), sbB = s2u(B32);

    // stage B once (48 rows x 28 uint4) — reused across NT b-tiles
    {
        const uint4* src = (const uint4*)(g_H + (size_t)c * NROWB * NWORDS);
        for (int t = tid; t < NROWB * (NWORDS / 4); t += 256) {
            int row = t / (NWORDS / 4), q = t % (NWORDS / 4);
            *(uint4*)(B32 + row * RSTRIDE + q * 4) = src[t];
        }
    }

    const uint32_t aoff = ((uint32_t)(lane & 15)) * RSTRIDE * 4 + ((lane >> 4) << 4);
    const uint32_t boff = ((uint32_t)((lane & 7) + ((lane >> 4) << 3))) * RSTRIDE * 4 +
                          (((lane >> 3) & 1) << 4);
    const uint32_t abase = sbA + (uint32_t)(warp * 16) * RSTRIDE * 4 + aoff;
    const int g = lane >> 2, tig = lane & 3;
    const int r0 = warp * 16 + g;

    for (int t = 0; t < NT; t++) {
        const int b0 = (blockIdx.x * NT + t) << 7;

        __syncthreads();   // prior tile's LDSM/epilogue reads done (covers B staging on t=0)

        // stage y tile (12-wide, zero-padded) + build A (2 threads per row)
        for (int u = tid; u < 128 * 12; u += 256) {
            int row = u / 12, e = u % 12;
            sy[u] = (e < EDIM) ? y[(size_t)(b0 + row) * EDIM + e] : 0.f;
        }
        {
            const int row = tid >> 1, half = tid & 1;
            float xr[NI], p[45];
            const float* xp = x + ((size_t)(b0 + row) * CDIM + c) * NI;
#pragma unroll
            for (int i = 0; i < NI; i++) xr[i] = xp[i];
            int pc = 0;
#pragma unroll
            for (int i = 0; i < NI; i++)
#pragma unroll
                for (int j = i; j < NI; j++) p[pc++] = xr[i] * xr[j];
            uint4* dst = (uint4*)(A32 + row * RSTRIDE);
            if (half == 0) build_range<0, 14>(dst, p, xr);
            else           build_range<14, 28>(dst, p, xr);
        }
        __syncthreads();

        float acc[6][4];
#pragma unroll
        for (int n = 0; n < 6; n++)
#pragma unroll
            for (int d = 0; d < 4; d++) acc[n][d] = 0.f;

        // single pass over K, N=48 (hi only)
#pragma unroll 2
        for (int k = 0; k < 14; k++) {
            uint32_t af[4], bf[3][4];
            LDSM4(af, abase + k * 32);
#pragma unroll
            for (int gq = 0; gq < 3; gq++)
                LDSM4(bf[gq], sbB + (uint32_t)(gq * 16) * RSTRIDE * 4 + k * 32 + boff);
#pragma unroll
            for (int np = 0; np < 6; np++)
                MMA16816(acc[np], af, bf[np >> 1][(np & 1) * 2], bf[np >> 1][(np & 1) * 2 + 1]);
        }

        // epilogue: scale by y, reduce 12 e-cols per channel across the 4 tig lanes
        float res[2][4] = { {0.f, 0.f, 0.f, 0.f}, {0.f, 0.f, 0.f, 0.f} };
#pragma unroll
        for (int np = 0; np < 6; np++) {
            int m0 = np * 8 + tig * 2, m1 = m0 + 1;
            int ch0 = m0 / 12, e0 = m0 % 12;
            int ch1 = m1 / 12, e1 = m1 % 12;
            res[0][ch0] += acc[np][0] * sy[r0 * 12 + e0];
            res[0][ch1] += acc[np][1] * sy[r0 * 12 + e1];
            res[1][ch0] += acc[np][2] * sy[(r0 + 8) * 12 + e0];
            res[1][ch1] += acc[np][3] * sy[(r0 + 8) * 12 + e1];
        }
#pragma unroll
        for (int d = 1; d <= 2; d <<= 1)
#pragma unroll
            for (int h = 0; h < 2; h++)
#pragma unroll
                for (int q = 0; q < 4; q++)
                    res[h][q] += __shfl_xor_sync(0xffffffffu, res[h][q], d);

        if (tig == 0) {
#pragma unroll
            for (int h = 0; h < 2; h++) {
                size_t b = (size_t)(b0 + r0 + h * 8);
                out[b * 1024 + c] = res[h][0];
                out[b * 1024 + 256 + c * 3 + 0] = res[h][1];
                out[b * 1024 + 256 + c * 3 + 1] = res[h][2];
                out[b * 1024 + 256 + c * 3 + 2] = res[h][3];
            }
        }
    }
}

extern "C" void kernel_launch(void* const* d_in, const int* in_sizes, int n_in,
                              void* d_out, int out_size) {
    const float* x   = (const float*)d_in[0];
    const float* y   = (const float*)d_in[1];
    const float* U1s = (const float*)d_in[2];
    const float* U2s = (const float*)d_in[3];
    const float* U3s = (const float*)d_in[4];
    const float* U1v = (const float*)d_in[5];
    const float* U2v = (const float*)d_in[6];
    const float* U3v = (const float*)d_in[7];
    const float* W1s = (const float*)d_in[8];
    const float* W2s = (const float*)d_in[9];
    const float* W3s = (const float*)d_in[10];
    const float* W1v = (const float*)d_in[11];
    const float* W2v = (const float*)d_in[12];
    const float* W3v = (const float*)d_in[13];
    float* out = (float*)d_out;

    const int B = in_sizes[0] / (CDIM * NI);  // 2048
    const int ntile = B / 128;                 // 16

    cudaFuncSetAttribute(sc_mma_kernel, cudaFuncAttributeMaxDynamicSharedMemorySize, SMTOT);

    const int total = 4 * NM3 * ST3 + 4 * NM2 * 4;
    precompute_kernel<<<(total + 255) / 256, 256>>>(U2s, U3s, U2v, U3v);
    hbuild_kernel<<<CDIM * 4, 192>>>(U1s, U1v, W1s, W2s, W3s, W1v, W2v, W3v);
    sc_mma_kernel<<<dim3(ntile / NT, CDIM), 256, SMTOT>>>(x, y, out);
}

// round 17
// speedup vs baseline: 1.4391x; 1.0616x over previous
#include <cuda_runtime.h>
#include <cuda_fp16.h>
#include <cstdint>

#define NI 9
#define NM3 165
#define NM2 45
#define ST3 32
#define CDIM 256
#define EDIM 10
#define NROWB 48              // B rows: n = ch*12 + e (e>=10 zero pad), fp16 hi only
#define NWORDS 112            // 224 fp16 = 112 u32 words per row
#define RSTRIDE 116           // row stride in u32 words — ldmatrix conflict-free
#define NT 2                  // b-tiles per CTA (smaller CTAs -> less tail quantization)
#define SMB 59392             // A: 128*116*4
#define SMY 81664             // B: 48*116*4 = 22272
#define SMTOT 87808           // + y: 128*12*4 = 6144

__device__ __align__(16) float g_T3[4][NM3 * ST3];
__device__ __align__(16) float g_T2[4][NM2 * 4];
__device__ __align__(16) uint32_t g_H[CDIM * NROWB * NWORDS];   // 5.5 MB

// ---------------- proven symmetrization precompute ----------------
__device__ __forceinline__ void decode3(int m, int& i, int& j, int& l) {
    int cnt = 0;
    for (int a = 0; a < NI; a++) for (int b = a; b < NI; b++) for (int c = b; c < NI; c++) {
        if (cnt == m) { i = a; j = b; l = c; return; } cnt++;
    }
    i = j = l = 0;
}
__device__ __forceinline__ void decode2(int m, int& i, int& j) {
    int cnt = 0;
    for (int a = 0; a < NI; a++) for (int b = a; b < NI; b++) {
        if (cnt == m) { i = a; j = b; return; } cnt++;
    }
    i = j = 0;
}
__global__ void precompute_kernel(const float* __restrict__ U2s, const float* __restrict__ U3s,
                                  const float* __restrict__ U2v, const float* __restrict__ U3v) {
    int t = blockIdx.x * blockDim.x + threadIdx.x;
    const int N3 = 4 * NM3 * ST3, N2 = 4 * NM2 * 4;
    if (t < N3) {
        int pass = t / (NM3 * ST3), r = t % (NM3 * ST3), m = r / ST3, k = r % ST3;
        int K = (pass == 0) ? 23 : 30;
        float val = 0.f;
        if (k < K) {
            int i, j, l; decode3(m, i, j, l);
            int pi[6] = { i, i, j, j, l, l }, pj[6] = { j, l, i, l, i, j }, pl[6] = { l, j, l, i, j, i };
            const float* base = (pass == 0) ? U3s : (U3v + (pass - 1) * (NI * NI * NI * 30));
            int codes[6];
            for (int q = 0; q < 6; q++) {
                int code = (pi[q] * NI + pj[q]) * NI + pl[q];
                bool dup = false;
                for (int u = 0; u < q; u++) if (codes[u] == code) dup = true;
                codes[q] = code;
                if (!dup) val += base[code * K + k];
            }
        }
        g_T3[pass][m * ST3 + k] = val;
    } else if (t < N3 + N2) {
        int u = t - N3, pass = u / (NM2 * 4), r = u % (NM2 * 4), m = r / 4, k = r % 4;
        int K = (pass == 0) ? 3 : 4;
        float val = 0.f;
        if (k < K) {
            int i, j; decode2(m, i, j);
            const float* base = (pass == 0) ? U2s : (U2v + (pass - 1) * (NI * NI * 4));
            val = base[(i * NI + j) * K + k];
            if (i != j) val += base[(j * NI + i) * K + k];
        }
        g_T2[pass][m * 4 + k] = val;
    }
}

// ---------------- H build: fp16 hi only, rows n = ch*12 + e (e>=10 zeros) ----------------
__global__ void __launch_bounds__(192)
hbuild_kernel(const float* __restrict__ U1s, const float* __restrict__ U1v,
              const float* __restrict__ W1s, const float* __restrict__ W2s,
              const float* __restrict__ W3s, const float* __restrict__ W1v,
              const float* __restrict__ W2v, const float* __restrict__ W3v) {
    const int c = blockIdx.x >> 2, ch = blockIdx.x & 3;
    const int tid = threadIdx.x;
    __shared__ float sT3[NM3 * 33];
    __shared__ float sT2[NM2 * 4];
    __shared__ float sW3[12 * 30], sW2[12 * 4], sW1[12], sU1[9];

    const int K3 = ch ? 30 : 23, K2 = ch ? 4 : 3;
    const float* W3 = ch ? W3v : W3s;
    const float* W2 = ch ? W2v : W2s;
    const float* W1 = ch ? W1v : W1s;
    const float* U1 = ch ? (U1v + (ch - 1) * NI) : U1s;

    for (int idx = tid; idx < NM3 * 32; idx += 192)
        sT3[(idx >> 5) * 33 + (idx & 31)] = g_T3[ch][idx];
    for (int idx = tid; idx < NM2 * 4; idx += 192) sT2[idx] = g_T2[ch][idx];
    for (int idx = tid; idx < 12 * 30; idx += 192) {
        int e = idx / 30, kk = idx % 30;
        sW3[idx] = (e < EDIM && kk < K3) ? W3[(e * K3 + kk) * CDIM + c] : 0.f;
    }
    if (tid < 48) {
        int e = tid >> 2, kk = tid & 3;
        sW2[tid] = (e < EDIM && kk < K2) ? W2[(e * K2 + kk) * CDIM + c] : 0.f;
    }
    if (tid < 12) sW1[tid] = (tid < EDIM) ? W1[tid * CDIM + c] : 0.f;
    if (tid < 9) sU1[tid] = U1[tid];
    __syncthreads();

    const int e = tid / 16, t16 = tid % 16;   // e = 0..11 (rows e>=10 get zeros)
    const int n = ch * 12 + e;
    uint32_t* dstH = g_H + ((size_t)c * NROWB + n) * NWORDS;
    for (int it = 0; it < 7; it++) {
        int t = t16 + it * 16;
        float v[2];
#pragma unroll
        for (int h = 0; h < 2; h++) {
            int m = 2 * t + h;
            float s = 0.f;
            if (e < EDIM && m < 219) {
                if (m < 165) {
                    for (int kk = 0; kk < 30; kk++) s += sT3[m * 33 + kk] * sW3[e * 30 + kk];
                } else if (m < 210) {
                    int q = m - 165;
                    for (int kk = 0; kk < 4; kk++) s += sT2[q * 4 + kk] * sW2[e * 4 + kk];
                } else {
                    s = sU1[m - 210] * sW1[e];
                }
            }
            v[h] = s;
        }
        __half h0 = __float2half_rn(v[0]), h1 = __float2half_rn(v[1]);
        __half2 hh; hh.x = h0; hh.y = h1;
        dstH[t] = *reinterpret_cast<uint32_t*>(&hh);
    }
}

// ---------------- compile-time monomial maps for the A operand ----------------
__host__ __device__ constexpr int tri_p(int m) {
    int c = 0;
    for (int i = 0; i < 9; i++) for (int j = i; j < 9; j++) for (int l = j; l < 9; l++) {
        if (c == m) return i * 9 - i * (i - 1) / 2 + (j - i);
        c++;
    }
    return 0;
}
__host__ __device__ constexpr int tri_l(int m) {
    int c = 0;
    for (int i = 0; i < 9; i++) for (int j = i; j < 9; j++) for (int l = j; l < 9; l++) {
        if (c == m) return l;
        c++;
    }
    return 0;
}
template <int M>
__device__ __forceinline__ float elemv(const float* p, const float* xr) {
    if constexpr (M < 165) { constexpr int pi = tri_p(M), li = tri_l(M); return p[pi] * xr[li]; }
    else if constexpr (M < 210) return p[M - 165];
    else if constexpr (M < 219) return xr[M - 210];
    else return 0.f;
}
__device__ __forceinline__ uint32_t pack_f16(float v0, float v1) {
    uint32_t w;
    asm("cvt.rn.f16x2.f32 %0, %1, %2;" : "=r"(w) : "f"(v1), "f"(v0));
    return w;
}
template <int G, int G1>
__device__ __forceinline__ void build_range(uint4* dst, const float* p, const float* xr) {
    if constexpr (G < G1) {
        uint4 w;
        w.x = pack_f16(elemv<8 * G + 0>(p, xr), elemv<8 * G + 1>(p, xr));
        w.y = pack_f16(elemv<8 * G + 2>(p, xr), elemv<8 * G + 3>(p, xr));
        w.z = pack_f16(elemv<8 * G + 4>(p, xr), elemv<8 * G + 5>(p, xr));
        w.w = pack_f16(elemv<8 * G + 6>(p, xr), elemv<8 * G + 7>(p, xr));
        dst[G] = w;
        build_range<G + 1, G1>(dst, p, xr);
    }
}

// ---------------- mma helpers ----------------
__device__ __forceinline__ uint32_t s2u(const void* p) {
    uint32_t a;
    asm("{ .reg .u64 t; cvta.to.shared.u64 t, %1; cvt.u32.u64 %0, t; }" : "=r"(a) : "l"(p));
    return a;
}
#define LDSM4(r, addr) asm volatile( \
    "ldmatrix.sync.aligned.m8n8.x4.shared.b16 {%0,%1,%2,%3}, [%4];" \
    : "=r"((r)[0]), "=r"((r)[1]), "=r"((r)[2]), "=r"((r)[3]) : "r"(addr))
#define MMA16816(d, a, b0, b1) asm volatile( \
    "mma.sync.aligned.m16n8k16.row.col.f32.f16.f16.f32 " \
    "{%0,%1,%2,%3},{%4,%5,%6,%7},{%8,%9},{%0,%1,%2,%3};" \
    : "+f"((d)[0]), "+f"((d)[1]), "+f"((d)[2]), "+f"((d)[3]) \
    : "r"((a)[0]), "r"((a)[1]), "r"((a)[2]), "r"((a)[3]), "r"(b0), "r"(b1))

// ---------------- main kernel: 256 threads, CTA = (NT b-tiles, c), B hi-only ----------------
__global__ void __launch_bounds__(256)
sc_mma_kernel(const float* __restrict__ x, const float* __restrict__ y,
              float* __restrict__ out) {
    extern __shared__ __align__(16) char smem[];
    uint32_t* A32 = (uint32_t*)smem;
    uint32_t* B32 = (uint32_t*)(smem + SMB);
    float* sy = (float*)(smem + SMY);   // [128][12], e>=10 zero

    const int tid = threadIdx.x;
    const int lane = tid & 31, warp = tid >> 5;   // 8 warps, 16 rows each
    const int c = blockIdx.y;
    const uint32_t sbA = s2u(A32), sbB = s2u(B32);

    // stage B once (48 rows x 28 uint4) — reused across NT b-tiles
    {
        const uint4* src = (const uint4*)(g_H + (size_t)c * NROWB * NWORDS);
        for (int t = tid; t < NROWB * (NWORDS / 4); t += 256) {
            int row = t / (NWORDS / 4), q = t % (NWORDS / 4);
            *(uint4*)(B32 + row * RSTRIDE + q * 4) = src[t];
        }
    }

    const uint32_t aoff = ((uint32_t)(lane & 15)) * RSTRIDE * 4 + ((lane >> 4) << 4);
    const uint32_t boff = ((uint32_t)((lane & 7) + ((lane >> 4) << 3))) * RSTRIDE * 4 +
                          (((lane >> 3) & 1) << 4);
    const uint32_t abase = sbA + (uint32_t)(warp * 16) * RSTRIDE * 4 + aoff;
    const int g = lane >> 2, tig = lane & 3;
    const int r0 = warp * 16 + g;

    for (int t = 0; t < NT; t++) {
        const int b0 = (blockIdx.x * NT + t) << 7;

        __syncthreads();   // prior tile's LDSM/epilogue reads done (covers B staging on t=0)

        // stage y tile (12-wide, zero-padded) + build A (2 threads per row)
        for (int u = tid; u < 128 * 12; u += 256) {
            int row = u / 12, e = u % 12;
            sy[u] = (e < EDIM) ? y[(size_t)(b0 + row) * EDIM + e] : 0.f;
        }
        {
            const int row = tid >> 1, half = tid & 1;
            float xr[NI], p[45];
            const float* xp = x + ((size_t)(b0 + row) * CDIM + c) * NI;
#pragma unroll
            for (int i = 0; i < NI; i++) xr[i] = xp[i];
            int pc = 0;
#pragma unroll
            for (int i = 0; i < NI; i++)
#pragma unroll
                for (int j = i; j < NI; j++) p[pc++] = xr[i] * xr[j];
            uint4* dst = (uint4*)(A32 + row * RSTRIDE);
            if (half == 0) build_range<0, 14>(dst, p, xr);
            else           build_range<14, 28>(dst, p, xr);
        }
        __syncthreads();

        float acc[6][4];
#pragma unroll
        for (int n = 0; n < 6; n++)
#pragma unroll
            for (int d = 0; d < 4; d++) acc[n][d] = 0.f;

        // single pass over K, N=48 (hi only)
#pragma unroll 2
        for (int k = 0; k < 14; k++) {
            uint32_t af[4], bf[3][4];
            LDSM4(af, abase + k * 32);
#pragma unroll
            for (int gq = 0; gq < 3; gq++)
                LDSM4(bf[gq], sbB + (uint32_t)(gq * 16) * RSTRIDE * 4 + k * 32 + boff);
#pragma unroll
            for (int np = 0; np < 6; np++)
                MMA16816(acc[np], af, bf[np >> 1][(np & 1) * 2], bf[np >> 1][(np & 1) * 2 + 1]);
        }

        // epilogue: scale by y, reduce 12 e-cols per channel across the 4 tig lanes
        float res[2][4] = { {0.f, 0.f, 0.f, 0.f}, {0.f, 0.f, 0.f, 0.f} };
#pragma unroll
        for (int np = 0; np < 6; np++) {
            int m0 = np * 8 + tig * 2, m1 = m0 + 1;
            int ch0 = m0 / 12, e0 = m0 % 12;
            int ch1 = m1 / 12, e1 = m1 % 12;
            res[0][ch0] += acc[np][0] * sy[r0 * 12 + e0];
            res[0][ch1] += acc[np][1] * sy[r0 * 12 + e1];
            res[1][ch0] += acc[np][2] * sy[(r0 + 8) * 12 + e0];
            res[1][ch1] += acc[np][3] * sy[(r0 + 8) * 12 + e1];
        }
#pragma unroll
        for (int d = 1; d <= 2; d <<= 1)
#pragma unroll
            for (int h = 0; h < 2; h++)
#pragma unroll
                for (int q = 0; q < 4; q++)
                    res[h][q] += __shfl_xor_sync(0xffffffffu, res[h][q], d);

        if (tig == 0) {
#pragma unroll
            for (int h = 0; h < 2; h++) {
                size_t b = (size_t)(b0 + r0 + h * 8);
                out[b * 1024 + c] = res[h][0];
                out[b * 1024 + 256 + c * 3 + 0] = res[h][1];
                out[b * 1024 + 256 + c * 3 + 1] = res[h][2];
                out[b * 1024 + 256 + c * 3 + 2] = res[h][3];
            }
        }
    }
}

extern "C" void kernel_launch(void* const* d_in, const int* in_sizes, int n_in,
                              void* d_out, int out_size) {
    const float* x   = (const float*)d_in[0];
    const float* y   = (const float*)d_in[1];
    const float* U1s = (const float*)d_in[2];
    const float* U2s = (const float*)d_in[3];
    const float* U3s = (const float*)d_in[4];
    const float* U1v = (const float*)d_in[5];
    const float* U2v = (const float*)d_in[6];
    const float* U3v = (const float*)d_in[7];
    const float* W1s = (const float*)d_in[8];
    const float* W2s = (const float*)d_in[9];
    const float* W3s = (const float*)d_in[10];
    const float* W1v = (const float*)d_in[11];
    const float* W2v = (const float*)d_in[12];
    const float* W3v = (const float*)d_in[13];
    float* out = (float*)d_out;

    const int B = in_sizes[0] / (CDIM * NI);  // 2048
    const int ntile = B / 128;                 // 16

    cudaFuncSetAttribute(sc_mma_kernel, cudaFuncAttributeMaxDynamicSharedMemorySize, SMTOT);

    const int total = 4 * NM3 * ST3 + 4 * NM2 * 4;
    precompute_kernel<<<(total + 255) / 256, 256>>>(U2s, U3s, U2v, U3v);
    hbuild_kernel<<<CDIM * 4, 192>>>(U1s, U1v, W1s, W2s, W3s, W1v, W2v, W3v);
    sc_mma_kernel<<<dim3(ntile / NT, CDIM), 256, SMTOT>>>(x, y, out);
}